// round 10
// baseline (speedup 1.0000x reference)
#include <cuda_runtime.h>
#include <cuda_fp16.h>
#include <cstdint>

// Problem constants
#define T_LEN   4096
#define D_DIM   64
#define R_OUT   127
#define HALF_W  63

#define TT      128      // t rows per tile (M)
#define NS      256      // k halo rows staged (N); rows 254..255 zero
#define SROWS   254

// SMEM layout: A tile + B tile + DEDICATED band buffer (no aliasing, no 2nd barrier)
#define SM_A      0
#define SM_B      (TT * 128)                 // 16384
#define SM_BAND   (SM_B + NS * 128)          // 49152
#define SM_TOTAL  (SM_BAND + TT * R_OUT * 4) // 49152 + 65024 = 114176

// standard SW128 swizzle (A tile)
#define SWZ(off) ((off) ^ (((off) >> 3) & 0x70))

// custom B swizzle: 16B-chunk permutation keyed on row bits the column
// permutation varies: pchunk = chunk ^ (((row>>3)&3) | ((row&1)<<2))
static __device__ __forceinline__ uint32_t bswz(uint32_t row) {
    return ((row >> 3) & 3u) | ((row & 1u) << 2);
}

static __device__ __forceinline__ uint32_t smem_u32(const void* p) {
    uint32_t a;
    asm("{ .reg .u64 t; cvta.to.shared.u64 t, %1; cvt.u32.u64 %0, t; }" : "=r"(a) : "l"(p));
    return a;
}

// fp32x4 -> packed fp16x2 pair (round once)
static __device__ __forceinline__ void conv4h(float4 v, uint32_t& h0, uint32_t& h1) {
    __half2 a = __floats2half2_rn(v.x, v.y);
    __half2 b = __floats2half2_rn(v.z, v.w);
    h0 = *reinterpret_cast<uint32_t*>(&a);
    h1 = *reinterpret_cast<uint32_t*>(&b);
}

#define LDSM_X4(r0, r1, r2, r3, a) \
    asm volatile("ldmatrix.sync.aligned.m8n8.x4.shared.b16 {%0,%1,%2,%3}, [%4];" \
        : "=r"(r0), "=r"(r1), "=r"(r2), "=r"(r3) : "r"(a))

#define MMA16816(d, a0, a1, a2, a3, b0, b1) \
    asm volatile("mma.sync.aligned.m16n8k16.row.col.f32.f16.f16.f32 " \
        "{%0,%1,%2,%3}, {%4,%5,%6,%7}, {%8,%9}, {%0,%1,%2,%3};" \
        : "+f"(d[0]), "+f"(d[1]), "+f"(d[2]), "+f"(d[3]) \
        : "r"(a0), "r"(a1), "r"(a2), "r"(a3), "r"(b0), "r"(b1))

__global__ void __launch_bounds__(256, 2)
unfold_dot_hmma(const float* __restrict__ q,
                const float* __restrict__ k,
                float* __restrict__ out)
{
    extern __shared__ char smem[];
    const uint32_t sb = smem_u32(smem);
    const int tid = threadIdx.x;
    const int wid = tid >> 5;
    const int lid = tid & 31;
    const int t0  = blockIdx.x * TT;
    const int bh  = blockIdx.y;
    const int m0  = wid * 16;

    // ---- stage Q tile: 128 rows x 64 d -> fp16 (single product), SW128 ----
    const float4* qg = reinterpret_cast<const float4*>(q) +
                       ((size_t)bh * T_LEN + t0) * (D_DIM / 4);
    #pragma unroll
    for (int it = 0; it < 4; ++it) {
        int idx = tid + it * 256;          // 0..1023
        int row = idx >> 3;
        int g   = idx & 7;
        float4 v0 = qg[row * 16 + g * 2];
        float4 v1 = qg[row * 16 + g * 2 + 1];
        uint32_t h0, h1, h2, h3;
        conv4h(v0, h0, h1);
        conv4h(v1, h2, h3);
        uint32_t off = SWZ((uint32_t)(row * 128 + g * 16));
        *reinterpret_cast<uint4*>(smem + SM_A + off) = make_uint4(h0, h1, h2, h3);
    }

    // ---- stage K halo: 256 rows, fp16, custom bswz chunk swizzle ----
    const float4* kg = reinterpret_cast<const float4*>(k) +
                       (size_t)bh * T_LEN * (D_DIM / 4);
    #pragma unroll
    for (int it = 0; it < 8; ++it) {
        int idx  = tid + it * 256;         // 0..2047
        int srow = idx >> 3;
        int g    = idx & 7;
        int sg   = t0 - HALF_W + srow;
        float4 v0 = make_float4(0.f, 0.f, 0.f, 0.f);
        float4 v1 = v0;
        if (srow < SROWS && (unsigned)sg < T_LEN) {
            v0 = kg[sg * 16 + g * 2];
            v1 = kg[sg * 16 + g * 2 + 1];
        }
        uint32_t h0, h1, h2, h3;
        conv4h(v0, h0, h1);
        conv4h(v1, h2, h3);
        uint32_t off = (uint32_t)(srow * 128) + (((uint32_t)g ^ bswz(srow)) << 4);
        *reinterpret_cast<uint4*>(smem + SM_B + off) = make_uint4(h0, h1, h2, h3);
    }
    __syncthreads();           // only barrier in the kernel

    // ---- compute ----
    // Warp w: rows [m0, m0+16). Band cols [m0, m0+144): 4 n32 super-tiles of 4
    // column-permuted MMAs + 1 leftover n16 pair. D = Qh * Kh (1-product fp16).
    float acc[18][4];
    #pragma unroll
    for (int j = 0; j < 18; ++j)
        #pragma unroll
        for (int e = 0; e < 4; ++e) acc[j][e] = 0.f;

    // A lane address (standard)
    const int amat = lid >> 3;
    const uint32_t a_base = (uint32_t)((m0 + (amat & 1) * 8 + (lid & 7)) * 128
                                       + (amat >> 1) * 16);

    // B permuted lane constants (as R8)
    const int r7    = lid & 7;
    const int khalf = (lid >> 3) & 1;
    const int phi   = (lid >> 4) & 1;
    const uint32_t row0 = (uint32_t)(m0 + 8 * (r7 >> 1) + (r7 & 1) + 2 * phi);
    const uint32_t row1 = row0 + 4;
    const uint32_t swz0 = bswz(row0);
    const uint32_t swz1 = bswz(row1);
    const uint32_t rowL = (uint32_t)(m0 + 128 + 4 * (r7 >> 1) + (r7 & 1) + 2 * phi);
    const uint32_t swzL = bswz(rowL);

    #pragma unroll
    for (int kc = 0; kc < 4; ++kc) {
        uint32_t ah0, ah1, ah2, ah3;
        LDSM_X4(ah0, ah1, ah2, ah3, sb + SM_A + SWZ(a_base + kc * 32));

        const uint32_t c0 = (uint32_t)(2 * kc + khalf);
        uint32_t ad0 = sb + SM_B + row0 * 128 + ((c0 ^ swz0) << 4);
        uint32_t ad1 = sb + SM_B + row1 * 128 + ((c0 ^ swz1) << 4);
        const uint32_t adL = sb + SM_B + rowL * 128 + ((c0 ^ swzL) << 4);

        // software-pipelined B loads (depth 1)
        uint32_t bA0, bA1, bA2, bA3, bB0, bB1, bB2, bB3;
        LDSM_X4(bA0, bA1, bA2, bA3, ad0);
        #pragma unroll
        for (int s = 0; s < 4; ++s) {
            LDSM_X4(bB0, bB1, bB2, bB3, ad1);
            MMA16816(acc[4 * s + 0], ah0, ah1, ah2, ah3, bA0, bA1);
            MMA16816(acc[4 * s + 1], ah0, ah1, ah2, ah3, bA2, bA3);
            uint32_t nxt = (s < 3) ? (ad0 + 32 * 128) : adL;
            LDSM_X4(bA0, bA1, bA2, bA3, nxt);
            MMA16816(acc[4 * s + 2], ah0, ah1, ah2, ah3, bB0, bB1);
            MMA16816(acc[4 * s + 3], ah0, ah1, ah2, ah3, bB2, bB3);
            ad0 += 32 * 128;
            ad1 += 32 * 128;
        }
        // leftover n16 pair (bA holds adL data)
        MMA16816(acc[16], ah0, ah1, ah2, ah3, bA0, bA1);
        MMA16816(acc[17], ah0, ah1, ah2, ah3, bA2, bA3);
    }

    // ---- epilogue: warp-private conflict-free scatter (dedicated band, no sync) ----
    // acc[4s+p]: lane (a=lid>>2, b=lid&3, eh) -> D[i=m0+a+8eh][col=m0+32s+8b+2p (+1)]
    // band float index: i*126 + col (== i*127 + rr, rr = col - i)
    float* band = reinterpret_cast<float*>(smem + SM_BAND);
    {
        const int i0 = m0 + (lid >> 2);
        const int cb = lid & 3;
        #pragma unroll
        for (int s = 0; s < 4; ++s) {
            #pragma unroll
            for (int p = 0; p < 4; ++p) {
                int col = m0 + 32 * s + 8 * cb + 2 * p;
                #pragma unroll
                for (int eh = 0; eh < 2; ++eh) {
                    int i   = i0 + 8 * eh;
                    int idx = i * (R_OUT - 1) + col;
                    unsigned rr = (unsigned)(col - i);
                    float2 v = make_float2(acc[4 * s + p][2 * eh],
                                           acc[4 * s + p][2 * eh + 1]);
                    if (rr <= 125u) {
                        *reinterpret_cast<float2*>(band + idx) = v;
                    } else if (rr == 126u) {
                        band[idx] = v.x;
                    } else if (rr == 0xFFFFFFFFu) {
                        band[idx + 1] = v.y;
                    }
                }
            }
        }
        #pragma unroll
        for (int p = 0; p < 2; ++p) {
            int col = m0 + 128 + 4 * cb + 2 * p;
            #pragma unroll
            for (int eh = 0; eh < 2; ++eh) {
                int i   = i0 + 8 * eh;
                int idx = i * (R_OUT - 1) + col;
                unsigned rr = (unsigned)(col - i);
                float2 v = make_float2(acc[16 + p][2 * eh],
                                       acc[16 + p][2 * eh + 1]);
                if (rr <= 125u) {
                    *reinterpret_cast<float2*>(band + idx) = v;
                } else if (rr == 126u) {
                    band[idx] = v.x;
                } else if (rr == 0xFFFFFFFFu) {
                    band[idx + 1] = v.y;
                }
            }
        }
    }

    // ---- per-warp bulk store: 16 rows = contiguous 8128B slice ----
    __syncwarp();
    if (lid == 0) {
        asm volatile("fence.proxy.async.shared::cta;" ::: "memory");
        float* dst = out + ((size_t)bh * T_LEN + t0) * R_OUT + m0 * R_OUT;
        uint32_t src = sb + SM_BAND + (uint32_t)(m0 * R_OUT * 4);
        asm volatile("cp.async.bulk.global.shared::cta.bulk_group [%0], [%1], %2;"
                     :: "l"(dst), "r"(src), "r"((uint32_t)(16 * R_OUT * 4)) : "memory");
        asm volatile("cp.async.bulk.commit_group;" ::: "memory");
        asm volatile("cp.async.bulk.wait_group.read 0;" ::: "memory");
    }
}

extern "C" void kernel_launch(void* const* d_in, const int* in_sizes, int n_in,
                              void* d_out, int out_size)
{
    const float* q = (const float*)d_in[0];
    const float* k = (const float*)d_in[1];
    float* out     = (float*)d_out;

    int bh = in_sizes[0] / (T_LEN * D_DIM);   // 128

    cudaFuncSetAttribute(unfold_dot_hmma,
                         cudaFuncAttributeMaxDynamicSharedMemorySize, SM_TOTAL);

    dim3 grid(T_LEN / TT, bh);
    unfold_dot_hmma<<<grid, 256, SM_TOTAL>>>(q, k, out);
}

// round 11
// speedup vs baseline: 1.4181x; 1.4181x over previous
#include <cuda_runtime.h>
#include <cuda_fp16.h>
#include <cstdint>

// Problem constants
#define T_LEN   4096
#define D_DIM   64
#define R_OUT   127
#define HALF_W  63

#define TT      128      // t rows per tile (M)
#define NS      256      // k halo rows staged (N); rows 254..255 zero
#define SROWS   254

// SMEM layout: operands A+B (48 KB); band (63.5 KB) aliases the whole region
// after compute (guarded by __syncthreads). Total 64 KB/CTA -> 2 CTAs/SM with
// ~100 KB L1D left for the staging LDG stream (the R9/R10 regressions came
// from starving that carveout).
#define SM_A      0
#define SM_B      (TT * 128)                 // 16384
#define SM_BAND   0                          // aliased after compute
#define SM_TOTAL  65536

// standard SW128 swizzle (A tile)
#define SWZ(off) ((off) ^ (((off) >> 3) & 0x70))

// custom B swizzle: pchunk = chunk ^ (((row>>3)&3) | ((row&1)<<2))
static __device__ __forceinline__ uint32_t bswz(uint32_t row) {
    return ((row >> 3) & 3u) | ((row & 1u) << 2);
}

static __device__ __forceinline__ uint32_t smem_u32(const void* p) {
    uint32_t a;
    asm("{ .reg .u64 t; cvta.to.shared.u64 t, %1; cvt.u32.u64 %0, t; }" : "=r"(a) : "l"(p));
    return a;
}

// fp32x4 -> packed fp16x2 pair (round once)
static __device__ __forceinline__ void conv4h(float4 v, uint32_t& h0, uint32_t& h1) {
    __half2 a = __floats2half2_rn(v.x, v.y);
    __half2 b = __floats2half2_rn(v.z, v.w);
    h0 = *reinterpret_cast<uint32_t*>(&a);
    h1 = *reinterpret_cast<uint32_t*>(&b);
}

#define LDSM_X4(r0, r1, r2, r3, a) \
    asm volatile("ldmatrix.sync.aligned.m8n8.x4.shared.b16 {%0,%1,%2,%3}, [%4];" \
        : "=r"(r0), "=r"(r1), "=r"(r2), "=r"(r3) : "r"(a))

#define MMA16816(d, a0, a1, a2, a3, b0, b1) \
    asm volatile("mma.sync.aligned.m16n8k16.row.col.f32.f16.f16.f32 " \
        "{%0,%1,%2,%3}, {%4,%5,%6,%7}, {%8,%9}, {%0,%1,%2,%3};" \
        : "+f"(d[0]), "+f"(d[1]), "+f"(d[2]), "+f"(d[3]) \
        : "r"(a0), "r"(a1), "r"(a2), "r"(a3), "r"(b0), "r"(b1))

__global__ void __launch_bounds__(256, 2)
unfold_dot_hmma(const float* __restrict__ q,
                const float* __restrict__ k,
                float* __restrict__ out)
{
    extern __shared__ char smem[];
    const uint32_t sb = smem_u32(smem);
    const int tid = threadIdx.x;
    const int wid = tid >> 5;
    const int lid = tid & 31;
    const int t0  = blockIdx.x * TT;
    const int bh  = blockIdx.y;
    const int m0  = wid * 16;

    // ---- stage Q tile: 128 rows x 64 d -> fp16 (single product), SW128 ----
    const float4* qg = reinterpret_cast<const float4*>(q) +
                       ((size_t)bh * T_LEN + t0) * (D_DIM / 4);
    #pragma unroll
    for (int it = 0; it < 4; ++it) {
        int idx = tid + it * 256;          // 0..1023
        int row = idx >> 3;
        int g   = idx & 7;
        float4 v0 = qg[row * 16 + g * 2];
        float4 v1 = qg[row * 16 + g * 2 + 1];
        uint32_t h0, h1, h2, h3;
        conv4h(v0, h0, h1);
        conv4h(v1, h2, h3);
        uint32_t off = SWZ((uint32_t)(row * 128 + g * 16));
        *reinterpret_cast<uint4*>(smem + SM_A + off) = make_uint4(h0, h1, h2, h3);
    }

    // ---- stage K halo: 256 rows, fp16, custom bswz chunk swizzle ----
    const float4* kg = reinterpret_cast<const float4*>(k) +
                       (size_t)bh * T_LEN * (D_DIM / 4);
    #pragma unroll
    for (int it = 0; it < 8; ++it) {
        int idx  = tid + it * 256;         // 0..2047
        int srow = idx >> 3;
        int g    = idx & 7;
        int sg   = t0 - HALF_W + srow;
        float4 v0 = make_float4(0.f, 0.f, 0.f, 0.f);
        float4 v1 = v0;
        if (srow < SROWS && (unsigned)sg < T_LEN) {
            v0 = kg[sg * 16 + g * 2];
            v1 = kg[sg * 16 + g * 2 + 1];
        }
        uint32_t h0, h1, h2, h3;
        conv4h(v0, h0, h1);
        conv4h(v1, h2, h3);
        uint32_t off = (uint32_t)(srow * 128) + (((uint32_t)g ^ bswz(srow)) << 4);
        *reinterpret_cast<uint4*>(smem + SM_B + off) = make_uint4(h0, h1, h2, h3);
    }
    __syncthreads();

    // ---- compute: D = Qh * Kh (1-product fp16) ----
    // Warp w: rows [m0, m0+16). Band cols [m0, m0+144): 4 n32 super-tiles of 4
    // column-permuted MMAs + 1 leftover n16 pair (R8 permuted layout).
    float acc[18][4];
    #pragma unroll
    for (int j = 0; j < 18; ++j)
        #pragma unroll
        for (int e = 0; e < 4; ++e) acc[j][e] = 0.f;

    // A lane address (standard)
    const int amat = lid >> 3;
    const uint32_t a_base = (uint32_t)((m0 + (amat & 1) * 8 + (lid & 7)) * 128
                                       + (amat >> 1) * 16);

    // B permuted lane constants (as R8)
    const int r7    = lid & 7;
    const int khalf = (lid >> 3) & 1;
    const int phi   = (lid >> 4) & 1;
    const uint32_t row0 = (uint32_t)(m0 + 8 * (r7 >> 1) + (r7 & 1) + 2 * phi);
    const uint32_t row1 = row0 + 4;
    const uint32_t swz0 = bswz(row0);
    const uint32_t swz1 = bswz(row1);
    const uint32_t rowL = (uint32_t)(m0 + 128 + 4 * (r7 >> 1) + (r7 & 1) + 2 * phi);
    const uint32_t swzL = bswz(rowL);

    #pragma unroll
    for (int kc = 0; kc < 4; ++kc) {
        uint32_t ah0, ah1, ah2, ah3;
        LDSM_X4(ah0, ah1, ah2, ah3, sb + SM_A + SWZ(a_base + kc * 32));

        const uint32_t c0 = (uint32_t)(2 * kc + khalf);
        uint32_t ad0 = sb + SM_B + row0 * 128 + ((c0 ^ swz0) << 4);
        uint32_t ad1 = sb + SM_B + row1 * 128 + ((c0 ^ swz1) << 4);

        #pragma unroll
        for (int s = 0; s < 4; ++s) {
            uint32_t b0, b1, b2, b3;
            LDSM_X4(b0, b1, b2, b3, ad0);                 // MMAs p=0,1
            MMA16816(acc[4 * s + 0], ah0, ah1, ah2, ah3, b0, b1);
            MMA16816(acc[4 * s + 1], ah0, ah1, ah2, ah3, b2, b3);
            LDSM_X4(b0, b1, b2, b3, ad1);                 // MMAs p=2,3
            MMA16816(acc[4 * s + 2], ah0, ah1, ah2, ah3, b0, b1);
            MMA16816(acc[4 * s + 3], ah0, ah1, ah2, ah3, b2, b3);
            ad0 += 32 * 128;                               // +32 rows: swizzle-invariant
            ad1 += 32 * 128;
        }
        {   // leftover n16 pair
            uint32_t b0, b1, b2, b3;
            uint32_t adL = sb + SM_B + rowL * 128 + ((c0 ^ swzL) << 4);
            LDSM_X4(b0, b1, b2, b3, adL);
            MMA16816(acc[16], ah0, ah1, ah2, ah3, b0, b1);
            MMA16816(acc[17], ah0, ah1, ah2, ah3, b2, b3);
        }
    }

    __syncthreads();   // band aliases operand tiles

    // ---- epilogue: conflict-free paired scatter into smem band tile ----
    // acc[4s+p]: lane (a=lid>>2, b=lid&3, eh) -> D[i=m0+a+8eh][col=m0+32s+8b+2p (+1)]
    // band float index: i*126 + col (== i*127 + rr, rr = col - i)
    float* band = reinterpret_cast<float*>(smem + SM_BAND);
    {
        const int i0 = m0 + (lid >> 2);
        const int cb = lid & 3;
        #pragma unroll
        for (int s = 0; s < 4; ++s) {
            #pragma unroll
            for (int p = 0; p < 4; ++p) {
                int col = m0 + 32 * s + 8 * cb + 2 * p;
                #pragma unroll
                for (int eh = 0; eh < 2; ++eh) {
                    int i   = i0 + 8 * eh;
                    int idx = i * (R_OUT - 1) + col;
                    unsigned rr = (unsigned)(col - i);
                    float2 v = make_float2(acc[4 * s + p][2 * eh],
                                           acc[4 * s + p][2 * eh + 1]);
                    if (rr <= 125u) {
                        *reinterpret_cast<float2*>(band + idx) = v;
                    } else if (rr == 126u) {
                        band[idx] = v.x;
                    } else if (rr == 0xFFFFFFFFu) {
                        band[idx + 1] = v.y;
                    }
                }
            }
        }
        #pragma unroll
        for (int p = 0; p < 2; ++p) {
            int col = m0 + 128 + 4 * cb + 2 * p;
            #pragma unroll
            for (int eh = 0; eh < 2; ++eh) {
                int i   = i0 + 8 * eh;
                int idx = i * (R_OUT - 1) + col;
                unsigned rr = (unsigned)(col - i);
                float2 v = make_float2(acc[16 + p][2 * eh],
                                       acc[16 + p][2 * eh + 1]);
                if (rr <= 125u) {
                    *reinterpret_cast<float2*>(band + idx) = v;
                } else if (rr == 126u) {
                    band[idx] = v.x;
                } else if (rr == 0xFFFFFFFFu) {
                    band[idx + 1] = v.y;
                }
            }
        }
    }

    // ---- per-warp bulk store: warp w's 16 rows = contiguous 8128B slice ----
    __syncwarp();
    if (lid == 0) {
        asm volatile("fence.proxy.async.shared::cta;" ::: "memory");
        float* dst = out + ((size_t)bh * T_LEN + t0) * R_OUT + m0 * R_OUT;
        uint32_t src = sb + SM_BAND + (uint32_t)(m0 * R_OUT * 4);
        asm volatile("cp.async.bulk.global.shared::cta.bulk_group [%0], [%1], %2;"
                     :: "l"(dst), "r"(src), "r"((uint32_t)(16 * R_OUT * 4)) : "memory");
        asm volatile("cp.async.bulk.commit_group;" ::: "memory");
        asm volatile("cp.async.bulk.wait_group.read 0;" ::: "memory");
    }
}

extern "C" void kernel_launch(void* const* d_in, const int* in_sizes, int n_in,
                              void* d_out, int out_size)
{
    const float* q = (const float*)d_in[0];
    const float* k = (const float*)d_in[1];
    float* out     = (float*)d_out;

    int bh = in_sizes[0] / (T_LEN * D_DIM);   // 128

    cudaFuncSetAttribute(unfold_dot_hmma,
                         cudaFuncAttributeMaxDynamicSharedMemorySize, SM_TOTAL);

    dim3 grid(T_LEN / TT, bh);
    unfold_dot_hmma<<<grid, 256, SM_TOTAL>>>(q, k, out);
}